// round 16
// baseline (speedup 1.0000x reference)
#include <cuda_runtime.h>
#include <cuda_fp16.h>
#include <cstdint>

// flows:  [B=4, L=32, 2,  H=128, W=128] fp32 planar input. Internal flow
//         scratch is interleaved float2 [bt][hw][2]; only step 1 reads the
//         planar input (in place, no transpose pass).
// images: [B=4, L=32, 16, H=128, W=128] fp32 planar in/out; internal state fp16
//         channel-interleaved [bt][hw][16].
// pscan steps s = 1,2,4,8,16, no-copy routing:
//   step s: t in [s,2s) FINAL -> planar fp32 d_out (+ fp16 iF unless last step)
//           t in [2s,L)       -> fp16 scratch ping-pong
//   image reads j = t-s: j==0 -> iIn, 1<=j<s -> iF, j>=s -> prev scratch.
// Flow computed only for scratch-region slices (final-region flow provably dead).
// Cache policy: single-use loads (cur/flow-cur) use __ldcs (evict-first);
// all state stores use __stcs (streaming); gather taps keep default caching
// so they own L1/L2.

constexpr int B  = 4;
constexpr int L  = 32;
constexpr int C  = 16;
constexpr int H  = 128;
constexpr int W  = 128;
constexpr int HW = H * W;
constexpr int FSTR = 2 * HW;
constexpr int ISTR = C * HW;

__device__ __align__(16) __half g_iIn[B * L * ISTR];
__device__ __align__(16) __half g_iF [B * L * ISTR];
__device__ __align__(16) __half g_iS0[B * L * ISTR];
__device__ __align__(16) __half g_iS1[B * L * ISTR];
__device__ float g_fS0[B * L * FSTR];   // interleaved float2
__device__ float g_fS1[B * L * FSTR];   // interleaved float2

struct GridS {
    int o00, o01, o10, o11;
    float w00, w01, w10, w11;   // border-pad weights (flows)
    float z00, z01, z10, z11;   // zeros-pad weights (images)
};

// Reference-exact grid computation. Conditional +/-2 wrap is bit-identical to
// the fmodf-based reference for v in [-4,4); fmodf fallback covers the rest.
__device__ __forceinline__ GridS make_grid(float fx, float fyv, int w, int h)
{
    GridS g;
    float gx = ((float)w + 0.5f) * (2.0f / W) - 1.0f + fx;
    float gy = ((float)h + 0.5f) * (2.0f / H) - 1.0f + fyv;

    float v = gx + 1.0f;
    if (v >= 4.0f || v < -4.0f) {
        v = fmodf(v, 2.0f);
    }
    if (v >= 2.0f) v -= 2.0f;
    if (v >= 2.0f) v -= 2.0f;
    if (v < 0.0f)  v += 2.0f;
    if (v < 0.0f)  v += 2.0f;
    float gxw = v - 1.0f;

    float x  = (gxw + 1.0f) * (0.5f * W) - 0.5f;
    float yy = (gy  + 1.0f) * (0.5f * H) - 0.5f;

    float x0f = floorf(x);
    float y0f = floorf(yy);
    float wx = x - x0f;
    float wy = yy - y0f;
    int x0 = (int)x0f, y0 = (int)y0f;
    int x1 = x0 + 1,   y1 = y0 + 1;

    int x0c = min(max(x0, 0), W - 1);
    int x1c = min(max(x1, 0), W - 1);
    int y0c = min(max(y0, 0), H - 1);
    int y1c = min(max(y1, 0), H - 1);

    g.w00 = (1.0f - wx) * (1.0f - wy);
    g.w01 = wx * (1.0f - wy);
    g.w10 = (1.0f - wx) * wy;
    g.w11 = wx * wy;

    g.o00 = y0c * W + x0c;
    g.o01 = y0c * W + x1c;
    g.o10 = y1c * W + x0c;
    g.o11 = y1c * W + x1c;

    bool vx0 = (x0 >= 0) && (x0 < W);
    bool vx1 = (x1 >= 0) && (x1 < W);
    bool vy0 = (y0 >= 0) && (y0 < H);
    bool vy1 = (y1 >= 0) && (y1 < H);
    g.z00 = (vy0 && vx0) ? g.w00 : 0.0f;
    g.z01 = (vy0 && vx1) ? g.w01 : 0.0f;
    g.z10 = (vy1 && vx0) ? g.w10 : 0.0f;
    g.z11 = (vy1 && vx1) ? g.w11 : 0.0f;
    return g;
}

__device__ __forceinline__ unsigned h2u(__half2 h) {
    unsigned u; *(__half2*)&u = h; return u;
}
__device__ __forceinline__ __half2 u2h(unsigned u) {
    return *(__half2*)&u;
}

__device__ __forceinline__ void acc8(float* a, uint4 u, float z)
{
    float2 f;
    f = __half22float2(u2h(u.x)); a[0] += z * f.x; a[1] += z * f.y;
    f = __half22float2(u2h(u.y)); a[2] += z * f.x; a[3] += z * f.y;
    f = __half22float2(u2h(u.z)); a[4] += z * f.x; a[5] += z * f.y;
    f = __half22float2(u2h(u.w)); a[6] += z * f.x; a[7] += z * f.y;
}

__device__ __forceinline__ void set8(float* a, uint4 u)
{
    float2 f;
    f = __half22float2(u2h(u.x)); a[0] = f.x; a[1] = f.y;
    f = __half22float2(u2h(u.y)); a[2] = f.x; a[3] = f.y;
    f = __half22float2(u2h(u.z)); a[4] = f.x; a[5] = f.y;
    f = __half22float2(u2h(u.w)); a[6] = f.x; a[7] = f.y;
}

__device__ __forceinline__ uint4 pack8(const float* a)
{
    uint4 su;
    su.x = h2u(__floats2half2_rn(a[0], a[1]));
    su.y = h2u(__floats2half2_rn(a[2], a[3]));
    su.z = h2u(__floats2half2_rn(a[4], a[5]));
    su.w = h2u(__floats2half2_rn(a[6], a[7]));
    return su;
}

// ---- images: planar fp32 -> interleaved fp16 (+ t=0 planar passthrough) -----
__global__ __launch_bounds__(256)
void img_pre_kernel(const float* __restrict__ src, __half* __restrict__ dst,
                    float* __restrict__ out)
{
    __shared__ float sm[64 * 17];
    int tid = threadIdx.x;
    int pb = blockIdx.x * 64;
    size_t bt = blockIdx.y;
    bool is_t0 = ((bt & (L - 1)) == 0);
    const float* s = src + bt * ISTR;
    float* o = out + bt * ISTR;
    #pragma unroll
    for (int rr = 0; rr < 4; rr++) {
        int c = (tid >> 6) + rr * 4;
        int i = tid & 63;
        float v = __ldcs(&s[c * HW + pb + i]);
        sm[i * 17 + c] = v;
        if (is_t0) __stcs(&o[c * HW + pb + i], v);   // fused t=0 passthrough
    }
    __syncthreads();
    __half* d = dst + bt * ISTR + (size_t)pb * 16;
    int hbase = tid * 4;
    int px = hbase >> 4, ch = hbase & 15;
    __half2 h0 = __floats2half2_rn(sm[px * 17 + ch],     sm[px * 17 + ch + 1]);
    __half2 h1 = __floats2half2_rn(sm[px * 17 + ch + 2], sm[px * 17 + ch + 3]);
    uint2 u; u.x = h2u(h0); u.y = h2u(h1);
    __stcs(&((uint2*)d)[tid], u);
}

// ---- fused pscan step: 2 threads/pixel --------------------------------------
// FMODE: 0 = no flow (last step), 1 = interleaved flow state (s=2,4,8),
//        2 = planar input flow (s=1: read planar, lane-split taps, write interleaved).
template<int S, int FMODE>
__global__ __launch_bounds__(256)
void step_kernel(const __half* __restrict__ iIn, const __half* iFr, __half* iFw,
                 const __half* __restrict__ iprev, __half* __restrict__ iscr,
                 float* __restrict__ out,
                 const float* __restrict__ fprev, float* __restrict__ fscr)
{
    constexpr int Ls = L - S;
    constexpr bool LAST = (S == 16);
    __shared__ float sm[128 * 17];

    int tid = threadIdx.x;
    int half_ = tid & 1;                // 8-channel half / flow lane role
    int pl = tid >> 1;                  // 128 pixels per block
    int pb = blockIdx.x * 128, p = pb + pl;   // gridDim.x = 128
    int y = blockIdx.y;                 // B * Ls
    int b = y / Ls, trel = y % Ls;
    int t = S + trel, j = trel;
    bool final_t = (trel < S);          // uniform per block
    unsigned btI  = (unsigned)(b * L + t) * (unsigned)ISTR;
    unsigned btjI = (unsigned)(b * L + j) * (unsigned)ISTR;
    unsigned btF  = (unsigned)(b * L + t) * (unsigned)FSTR;
    unsigned btjF = (unsigned)(b * L + j) * (unsigned)FSTR;

    // current flow (grid source) -- single-use: evict-first
    float fx, fyv;
    if (FMODE == 2) {   // planar input layout
        fx  = __ldcs(&fprev[btF + p]);
        fyv = __ldcs(&fprev[btF + HW + p]);
    } else {            // interleaved float2
        float2 fc = __ldcs(&((const float2*)(fprev + btF))[p]);
        fx = fc.x; fyv = fc.y;
    }
    int w = p & (W - 1), h = p >> 7;
    GridS g = make_grid(fx, fyv, w, h);

    unsigned pixoff = (unsigned)p * 16 + half_ * 8;

    // current image value (fp16, 16B coalesced) -- single-use: evict-first
    uint4 cu = __ldcs((const uint4*)(iprev + btI + pixoff));
    float a[8];
    set8(a, cu);

    // gather: 4 taps, 16B each -- reuse-heavy: default caching
    const __half* ibase = (j == 0) ? iIn : (j < S) ? iFr : iprev;
    const __half* srcp = ibase + btjI + half_ * 8;
    uint4 u00 = *(const uint4*)(srcp + (unsigned)g.o00 * 16);
    uint4 u01 = *(const uint4*)(srcp + (unsigned)g.o01 * 16);
    uint4 u10 = *(const uint4*)(srcp + (unsigned)g.o10 * 16);
    uint4 u11 = *(const uint4*)(srcp + (unsigned)g.o11 * 16);
    acc8(a, u00, g.z00);
    acc8(a, u01, g.z01);
    acc8(a, u10, g.z10);
    acc8(a, u11, g.z11);

    if (final_t) {
        if (!LAST) {   // re-readable fp16 finals copy (streaming store)
            __stcs((uint4*)(iFw + btI + pixoff), pack8(a));
        }
        // exact fp32 planar d_out via conflict-free smem bounce
        int cb = half_ * 8;
        #pragma unroll
        for (int k = 0; k < 8; k++) sm[pl * 17 + cb + k] = a[k];
        __syncthreads();
        float* dst = out + btI;
        #pragma unroll
        for (int rr = 0; rr < 8; rr++) {
            int c = (tid >> 7) + rr * 2;
            int i = tid & 127;
            __stcs(&dst[c * HW + pb + i], sm[i * 17 + c]);
        }
    } else {
        __stcs((uint4*)(iscr + btI + pixoff), pack8(a));
    }

    // ---- flow: scratch-region slices only ----
    if (FMODE == 1 && !final_t) {
        // interleaved float2 taps on even lanes (single-region accesses)
        if (half_ == 0) {
            const float2* fsrc = (const float2*)(fprev + btjF);
            float2 t00 = fsrc[g.o00], t01 = fsrc[g.o01];
            float2 t10 = fsrc[g.o10], t11 = fsrc[g.o11];
            float nx = fx  + g.w00 * t00.x + g.w01 * t01.x + g.w10 * t10.x + g.w11 * t11.x;
            float ny = fyv + g.w00 * t00.y + g.w01 * t01.y + g.w10 * t10.y + g.w11 * t11.y;
            __stcs(&((float2*)(fscr + btF))[p], make_float2(nx, ny));
        }
    }
    if (FMODE == 2 && !final_t) {
        // planar input taps, lane-split (even lane x-plane, odd lane y-plane);
        // interleaved scalar store (coalesced). Same FMA order -> bit-identical.
        const float* fsrc = fprev + btjF + half_ * HW;
        float t00 = fsrc[g.o00], t01 = fsrc[g.o01];
        float t10 = fsrc[g.o10], t11 = fsrc[g.o11];
        float base = half_ ? fyv : fx;
        float nv = base + g.w00 * t00 + g.w01 * t01 + g.w10 * t10 + g.w11 * t11;
        __stcs(&fscr[btF + (unsigned)p * 2 + half_], nv);
    }
}

extern "C" void kernel_launch(void* const* d_in, const int* in_sizes, int n_in,
                              void* d_out, int out_size)
{
    const float* flows  = (const float*)d_in[0];
    const float* images = (const float*)d_in[1];
    if (n_in >= 2 && in_sizes[0] > in_sizes[1]) {
        flows  = (const float*)d_in[1];
        images = (const float*)d_in[0];
    }
    float* out = (float*)d_out;

    __half *iIn, *iF, *iS0, *iS1;
    float *fS0, *fS1;
    cudaGetSymbolAddress((void**)&iIn, g_iIn);
    cudaGetSymbolAddress((void**)&iF,  g_iF);
    cudaGetSymbolAddress((void**)&iS0, g_iS0);
    cudaGetSymbolAddress((void**)&iS1, g_iS1);
    cudaGetSymbolAddress((void**)&fS0, g_fS0);
    cudaGetSymbolAddress((void**)&fS1, g_fS1);

    img_pre_kernel<<<dim3(256, B * L), 256>>>(images, iIn, out);

    // s=1 reads planar input flows in place; writes interleaved flow scratch
    step_kernel<1, 2><<<dim3(128, B * 31), 256>>>(iIn, iF, iF, iIn, iS0, out,
                                                  flows, fS0);
    step_kernel<2, 1><<<dim3(128, B * 30), 256>>>(iIn, iF, iF, iS0, iS1, out,
                                                  fS0, fS1);
    step_kernel<4, 1><<<dim3(128, B * 28), 256>>>(iIn, iF, iF, iS1, iS0, out,
                                                  fS1, fS0);
    step_kernel<8, 1><<<dim3(128, B * 24), 256>>>(iIn, iF, iF, iS0, iS1, out,
                                                  fS0, fS1);
    step_kernel<16, 0><<<dim3(128, B * 16), 256>>>(iIn, iF, iF, iS1, iS0, out,
                                                   fS1, fS0);
}

// round 17
// speedup vs baseline: 1.1581x; 1.1581x over previous
#include <cuda_runtime.h>
#include <cuda_fp16.h>
#include <cstdint>

// flows:  [B=4, L=32, 2,  H=128, W=128] fp32 planar input. Internal flow
//         scratch is interleaved float2 [bt][hw][2]; only step 1 reads the
//         planar input (in place, no transpose pass).
// images: [B=4, L=32, 16, H=128, W=128] fp32 planar in/out; internal state fp16
//         channel-interleaved [bt][hw][16].
// pscan steps s = 1,2,4,8,16, no-copy routing:
//   step s: t in [s,2s) FINAL -> planar fp32 d_out (+ fp16 iF unless last step)
//           t in [2s,L)       -> fp16 scratch ping-pong
//   image reads j = t-s: j==0 -> iIn, 1<=j<s -> iF, j>=s -> prev scratch.
// Flow computed only for scratch-region slices (final-region flow provably dead).
// Cache policy: ONLY the planar d_out stores use __stcs (never re-read on
// device; frees L2 for the producer->consumer state chain). Everything else
// uses default caching — R16 proved that streaming-hinting the state stores
// destroys the cross-kernel L2 reuse this pipeline depends on.

constexpr int B  = 4;
constexpr int L  = 32;
constexpr int C  = 16;
constexpr int H  = 128;
constexpr int W  = 128;
constexpr int HW = H * W;
constexpr int FSTR = 2 * HW;
constexpr int ISTR = C * HW;

__device__ __align__(16) __half g_iIn[B * L * ISTR];
__device__ __align__(16) __half g_iF [B * L * ISTR];
__device__ __align__(16) __half g_iS0[B * L * ISTR];
__device__ __align__(16) __half g_iS1[B * L * ISTR];
__device__ float g_fS0[B * L * FSTR];   // interleaved float2
__device__ float g_fS1[B * L * FSTR];   // interleaved float2

struct GridS {
    int o00, o01, o10, o11;
    float w00, w01, w10, w11;   // border-pad weights (flows)
    float z00, z01, z10, z11;   // zeros-pad weights (images)
};

// Reference-exact grid computation. Conditional +/-2 wrap is bit-identical to
// the fmodf-based reference for v in [-4,4); fmodf fallback covers the rest.
__device__ __forceinline__ GridS make_grid(float fx, float fyv, int w, int h)
{
    GridS g;
    float gx = ((float)w + 0.5f) * (2.0f / W) - 1.0f + fx;
    float gy = ((float)h + 0.5f) * (2.0f / H) - 1.0f + fyv;

    float v = gx + 1.0f;
    if (v >= 4.0f || v < -4.0f) {
        v = fmodf(v, 2.0f);
    }
    if (v >= 2.0f) v -= 2.0f;
    if (v >= 2.0f) v -= 2.0f;
    if (v < 0.0f)  v += 2.0f;
    if (v < 0.0f)  v += 2.0f;
    float gxw = v - 1.0f;

    float x  = (gxw + 1.0f) * (0.5f * W) - 0.5f;
    float yy = (gy  + 1.0f) * (0.5f * H) - 0.5f;

    float x0f = floorf(x);
    float y0f = floorf(yy);
    float wx = x - x0f;
    float wy = yy - y0f;
    int x0 = (int)x0f, y0 = (int)y0f;
    int x1 = x0 + 1,   y1 = y0 + 1;

    int x0c = min(max(x0, 0), W - 1);
    int x1c = min(max(x1, 0), W - 1);
    int y0c = min(max(y0, 0), H - 1);
    int y1c = min(max(y1, 0), H - 1);

    g.w00 = (1.0f - wx) * (1.0f - wy);
    g.w01 = wx * (1.0f - wy);
    g.w10 = (1.0f - wx) * wy;
    g.w11 = wx * wy;

    g.o00 = y0c * W + x0c;
    g.o01 = y0c * W + x1c;
    g.o10 = y1c * W + x0c;
    g.o11 = y1c * W + x1c;

    bool vx0 = (x0 >= 0) && (x0 < W);
    bool vx1 = (x1 >= 0) && (x1 < W);
    bool vy0 = (y0 >= 0) && (y0 < H);
    bool vy1 = (y1 >= 0) && (y1 < H);
    g.z00 = (vy0 && vx0) ? g.w00 : 0.0f;
    g.z01 = (vy0 && vx1) ? g.w01 : 0.0f;
    g.z10 = (vy1 && vx0) ? g.w10 : 0.0f;
    g.z11 = (vy1 && vx1) ? g.w11 : 0.0f;
    return g;
}

__device__ __forceinline__ unsigned h2u(__half2 h) {
    unsigned u; *(__half2*)&u = h; return u;
}
__device__ __forceinline__ __half2 u2h(unsigned u) {
    return *(__half2*)&u;
}

__device__ __forceinline__ void acc8(float* a, uint4 u, float z)
{
    float2 f;
    f = __half22float2(u2h(u.x)); a[0] += z * f.x; a[1] += z * f.y;
    f = __half22float2(u2h(u.y)); a[2] += z * f.x; a[3] += z * f.y;
    f = __half22float2(u2h(u.z)); a[4] += z * f.x; a[5] += z * f.y;
    f = __half22float2(u2h(u.w)); a[6] += z * f.x; a[7] += z * f.y;
}

__device__ __forceinline__ void set8(float* a, uint4 u)
{
    float2 f;
    f = __half22float2(u2h(u.x)); a[0] = f.x; a[1] = f.y;
    f = __half22float2(u2h(u.y)); a[2] = f.x; a[3] = f.y;
    f = __half22float2(u2h(u.z)); a[4] = f.x; a[5] = f.y;
    f = __half22float2(u2h(u.w)); a[6] = f.x; a[7] = f.y;
}

__device__ __forceinline__ uint4 pack8(const float* a)
{
    uint4 su;
    su.x = h2u(__floats2half2_rn(a[0], a[1]));
    su.y = h2u(__floats2half2_rn(a[2], a[3]));
    su.z = h2u(__floats2half2_rn(a[4], a[5]));
    su.w = h2u(__floats2half2_rn(a[6], a[7]));
    return su;
}

// ---- images: planar fp32 -> interleaved fp16 (+ t=0 planar passthrough) -----
__global__ __launch_bounds__(256)
void img_pre_kernel(const float* __restrict__ src, __half* __restrict__ dst,
                    float* __restrict__ out)
{
    __shared__ float sm[64 * 17];
    int tid = threadIdx.x;
    int pb = blockIdx.x * 64;
    size_t bt = blockIdx.y;
    bool is_t0 = ((bt & (L - 1)) == 0);
    const float* s = src + bt * ISTR;
    float* o = out + bt * ISTR;
    #pragma unroll
    for (int rr = 0; rr < 4; rr++) {
        int c = (tid >> 6) + rr * 4;
        int i = tid & 63;
        float v = s[c * HW + pb + i];
        sm[i * 17 + c] = v;
        if (is_t0) __stcs(&o[c * HW + pb + i], v);   // d_out: never re-read
    }
    __syncthreads();
    __half* d = dst + bt * ISTR + (size_t)pb * 16;
    int hbase = tid * 4;
    int px = hbase >> 4, ch = hbase & 15;
    __half2 h0 = __floats2half2_rn(sm[px * 17 + ch],     sm[px * 17 + ch + 1]);
    __half2 h1 = __floats2half2_rn(sm[px * 17 + ch + 2], sm[px * 17 + ch + 3]);
    uint2 u; u.x = h2u(h0); u.y = h2u(h1);
    ((uint2*)d)[tid] = u;   // default: step1 reads this through L2
}

// ---- fused pscan step: 2 threads/pixel --------------------------------------
// FMODE: 0 = no flow (last step), 1 = interleaved flow state (s=2,4,8),
//        2 = planar input flow (s=1: read planar, lane-split taps, write interleaved).
template<int S, int FMODE>
__global__ __launch_bounds__(256)
void step_kernel(const __half* __restrict__ iIn, const __half* iFr, __half* iFw,
                 const __half* __restrict__ iprev, __half* __restrict__ iscr,
                 float* __restrict__ out,
                 const float* __restrict__ fprev, float* __restrict__ fscr)
{
    constexpr int Ls = L - S;
    constexpr bool LAST = (S == 16);
    __shared__ float sm[128 * 17];

    int tid = threadIdx.x;
    int half_ = tid & 1;                // 8-channel half / flow lane role
    int pl = tid >> 1;                  // 128 pixels per block
    int pb = blockIdx.x * 128, p = pb + pl;   // gridDim.x = 128
    int y = blockIdx.y;                 // B * Ls
    int b = y / Ls, trel = y % Ls;
    int t = S + trel, j = trel;
    bool final_t = (trel < S);          // uniform per block
    unsigned btI  = (unsigned)(b * L + t) * (unsigned)ISTR;
    unsigned btjI = (unsigned)(b * L + j) * (unsigned)ISTR;
    unsigned btF  = (unsigned)(b * L + t) * (unsigned)FSTR;
    unsigned btjF = (unsigned)(b * L + j) * (unsigned)FSTR;

    // current flow (grid source)
    float fx, fyv;
    if (FMODE == 2) {   // planar input layout
        fx  = fprev[btF + p];
        fyv = fprev[btF + HW + p];
    } else {            // interleaved float2
        float2 fc = ((const float2*)(fprev + btF))[p];
        fx = fc.x; fyv = fc.y;
    }
    int w = p & (W - 1), h = p >> 7;
    GridS g = make_grid(fx, fyv, w, h);

    unsigned pixoff = (unsigned)p * 16 + half_ * 8;

    // current image value (fp16, 16B coalesced)
    uint4 cu = *(const uint4*)(iprev + btI + pixoff);
    float a[8];
    set8(a, cu);

    // gather: 4 taps, 16B each
    const __half* ibase = (j == 0) ? iIn : (j < S) ? iFr : iprev;
    const __half* srcp = ibase + btjI + half_ * 8;
    uint4 u00 = *(const uint4*)(srcp + (unsigned)g.o00 * 16);
    uint4 u01 = *(const uint4*)(srcp + (unsigned)g.o01 * 16);
    uint4 u10 = *(const uint4*)(srcp + (unsigned)g.o10 * 16);
    uint4 u11 = *(const uint4*)(srcp + (unsigned)g.o11 * 16);
    acc8(a, u00, g.z00);
    acc8(a, u01, g.z01);
    acc8(a, u10, g.z10);
    acc8(a, u11, g.z11);

    if (final_t) {
        if (!LAST) {   // re-readable fp16 finals copy (default caching)
            *(uint4*)(iFw + btI + pixoff) = pack8(a);
        }
        // exact fp32 planar d_out via conflict-free smem bounce;
        // d_out lines are never re-read -> streaming store
        int cb = half_ * 8;
        #pragma unroll
        for (int k = 0; k < 8; k++) sm[pl * 17 + cb + k] = a[k];
        __syncthreads();
        float* dst = out + btI;
        #pragma unroll
        for (int rr = 0; rr < 8; rr++) {
            int c = (tid >> 7) + rr * 2;
            int i = tid & 127;
            __stcs(&dst[c * HW + pb + i], sm[i * 17 + c]);
        }
    } else {
        *(uint4*)(iscr + btI + pixoff) = pack8(a);   // default: next step reads it
    }

    // ---- flow: scratch-region slices only ----
    if (FMODE == 1 && !final_t) {
        // interleaved float2 taps on even lanes (single-region accesses)
        if (half_ == 0) {
            const float2* fsrc = (const float2*)(fprev + btjF);
            float2 t00 = fsrc[g.o00], t01 = fsrc[g.o01];
            float2 t10 = fsrc[g.o10], t11 = fsrc[g.o11];
            float nx = fx  + g.w00 * t00.x + g.w01 * t01.x + g.w10 * t10.x + g.w11 * t11.x;
            float ny = fyv + g.w00 * t00.y + g.w01 * t01.y + g.w10 * t10.y + g.w11 * t11.y;
            ((float2*)(fscr + btF))[p] = make_float2(nx, ny);
        }
    }
    if (FMODE == 2 && !final_t) {
        // planar input taps, lane-split (even lane x-plane, odd lane y-plane);
        // interleaved scalar store (coalesced). Same FMA order -> bit-identical.
        const float* fsrc = fprev + btjF + half_ * HW;
        float t00 = fsrc[g.o00], t01 = fsrc[g.o01];
        float t10 = fsrc[g.o10], t11 = fsrc[g.o11];
        float base = half_ ? fyv : fx;
        float nv = base + g.w00 * t00 + g.w01 * t01 + g.w10 * t10 + g.w11 * t11;
        fscr[btF + (unsigned)p * 2 + half_] = nv;
    }
}

extern "C" void kernel_launch(void* const* d_in, const int* in_sizes, int n_in,
                              void* d_out, int out_size)
{
    const float* flows  = (const float*)d_in[0];
    const float* images = (const float*)d_in[1];
    if (n_in >= 2 && in_sizes[0] > in_sizes[1]) {
        flows  = (const float*)d_in[1];
        images = (const float*)d_in[0];
    }
    float* out = (float*)d_out;

    __half *iIn, *iF, *iS0, *iS1;
    float *fS0, *fS1;
    cudaGetSymbolAddress((void**)&iIn, g_iIn);
    cudaGetSymbolAddress((void**)&iF,  g_iF);
    cudaGetSymbolAddress((void**)&iS0, g_iS0);
    cudaGetSymbolAddress((void**)&iS1, g_iS1);
    cudaGetSymbolAddress((void**)&fS0, g_fS0);
    cudaGetSymbolAddress((void**)&fS1, g_fS1);

    img_pre_kernel<<<dim3(256, B * L), 256>>>(images, iIn, out);

    // s=1 reads planar input flows in place; writes interleaved flow scratch
    step_kernel<1, 2><<<dim3(128, B * 31), 256>>>(iIn, iF, iF, iIn, iS0, out,
                                                  flows, fS0);
    step_kernel<2, 1><<<dim3(128, B * 30), 256>>>(iIn, iF, iF, iS0, iS1, out,
                                                  fS0, fS1);
    step_kernel<4, 1><<<dim3(128, B * 28), 256>>>(iIn, iF, iF, iS1, iS0, out,
                                                  fS1, fS0);
    step_kernel<8, 1><<<dim3(128, B * 24), 256>>>(iIn, iF, iF, iS0, iS1, out,
                                                  fS0, fS1);
    step_kernel<16, 0><<<dim3(128, B * 16), 256>>>(iIn, iF, iF, iS1, iS0, out,
                                                   fS1, fS0);
}